// round 15
// baseline (speedup 1.0000x reference)
#include <cuda_runtime.h>
#include <cuda_bf16.h>
#include <math.h>
#include <stdint.h>

// Problem constants
#define BB 2
#define NN 1024
#define CC 512
#define HH 8
#define HD 64
#define NCLUS 8
#define SCALE 0.125f
#define EPS 1e-6f
#define EPS_N (1e-6f/1024.0f)
#define SC_CAP 256

#define OUT_ELEMS (BB*NN*CC)                       // 1,048,576
#define MAP_ELEMS ((size_t)BB*NCLUS*HH*NN*NN)      // 134,217,728
#define MAP_ROWS  131072                           // 128 bch * 1024 i

// Scratch (static device globals; no allocation allowed)
__device__ float g_Q[BB*NN*CC];
__device__ float g_Kb[BB*NN*CC];
__device__ float g_V[BB*NN*CC];
__device__ float g_O[BB*NN*CC];
__device__ float g_colsum[BB*CC];
__device__ float g_csp[16][BB*CC];
__device__ int   g_mem[BB*NCLUS*NN];
__device__ int   g_cnt[BB*NCLUS];
__device__ float g_Sc[(size_t)BB*NCLUS*HH*SC_CAP*SC_CAP];

// ---------------------------------------------------------------------------
// Deterministic cluster compaction: one warp per (b,c).
// ---------------------------------------------------------------------------
__global__ void compact_kernel(const int* __restrict__ idx,
                               int* __restrict__ mem, int* __restrict__ cnt)
{
    const int bc = blockIdx.x;
    const int b = bc >> 3, c = bc & 7;
    const int lane = threadIdx.x;
    int pos = 0;
    for (int t0 = 0; t0 < NN; t0 += 32) {
        int t = t0 + lane;
        int v = idx[b * NN + t];
        unsigned ball = __ballot_sync(0xffffffffu, v == c);
        if (v == c) {
            int r = __popc(ball & ((1u << lane) - 1u));
            mem[bc * NN + pos + r] = t;
        }
        pos += __popc(ball);
    }
    if (lane == 0) cnt[bc] = pos;
}

// ---------------------------------------------------------------------------
// Row-gated streaming fill: zero all NON-member map rows (idx-only dep).
// One 4KB row per block-iteration, 256 threads x float4.
// ---------------------------------------------------------------------------
__global__ void __launch_bounds__(256) fill_rows(const int* __restrict__ idx,
                                                 float4* __restrict__ map4)
{
    const float4 z = make_float4(0.f, 0.f, 0.f, 0.f);
    for (int g = blockIdx.x; g < MAP_ROWS; g += gridDim.x) {
        const int bch = g >> 10;
        const int i   = g & 1023;
        const int b   = bch >> 6;
        const int c   = (bch >> 3) & 7;
        if (__ldg(&idx[b * NN + i]) == c) continue;   // member row -> compose
        __stcs(&map4[(size_t)g * 256 + threadIdx.x], z);
    }
}

// ---------------------------------------------------------------------------
// Compose member rows: full 4KB row = zeros + Sc values at member columns.
// Disjoint from fill_rows (writes only member rows).
// ---------------------------------------------------------------------------
__global__ void __launch_bounds__(128) compose_rows(
    const float* __restrict__ Sc, const int* __restrict__ mem,
    const int* __restrict__ cnt, float* __restrict__ map)
{
    const int bch = blockIdx.y;
    const int bc = bch >> 3;
    int Mc = cnt[bc]; if (Mc > SC_CAP) Mc = SC_CAP;
    const int p = blockIdx.x;
    if (p >= Mc) return;

    __shared__ float rowbuf[NN];
    #pragma unroll
    for (int j = threadIdx.x; j < NN; j += 128) rowbuf[j] = 0.f;
    __syncthreads();

    const float* src = Sc + ((size_t)bch * SC_CAP + p) * SC_CAP;
    const int* memb = mem + bc * NN;
    for (int q = threadIdx.x; q < Mc; q += 128)
        rowbuf[memb[q]] = src[q];
    __syncthreads();

    const int i = memb[p];
    float4* dst = reinterpret_cast<float4*>(map + ((size_t)bch * NN + i) * NN);
    const float4* s4 = reinterpret_cast<const float4*>(rowbuf);
    #pragma unroll
    for (int j = threadIdx.x; j < NN / 4; j += 128)
        __stcs(&dst[j], s4[j]);
}

// ---------------------------------------------------------------------------
// TF32 helpers (3xTF32 split)
// ---------------------------------------------------------------------------
__device__ __forceinline__ void tf32_pair(float x, uint32_t& hi, uint32_t& lo)
{
    asm("cvt.rna.tf32.f32 %0, %1;" : "=r"(hi) : "f"(x));
    float r = x - __uint_as_float(hi);
    asm("cvt.rna.tf32.f32 %0, %1;" : "=r"(lo) : "f"(r));
}

__device__ __forceinline__ void mma8(float* c, const uint32_t* a, const uint32_t* b)
{
    asm volatile(
        "mma.sync.aligned.m16n8k8.row.col.f32.tf32.tf32.f32 "
        "{%0,%1,%2,%3}, {%4,%5,%6,%7}, {%8,%9}, {%0,%1,%2,%3};"
        : "+f"(c[0]), "+f"(c[1]), "+f"(c[2]), "+f"(c[3])
        : "r"(a[0]), "r"(a[1]), "r"(a[2]), "r"(a[3]), "r"(b[0]), "r"(b[1]));
}

// ---------------------------------------------------------------------------
// TF32 GEMM body: out[m,n] = sum_k X[m,k]*W[n,k] (+bias). K=N=512.
// ---------------------------------------------------------------------------
#define SMS 136

__device__ __forceinline__ void gemm_tf32_body(
    const float* __restrict__ X, const float* __restrict__ W,
    const float* __restrict__ bias, float* __restrict__ out,
    int m0, int n0, bool has_bias)
{
    __shared__ uint32_t As_h[16][SMS], As_l[16][SMS];
    __shared__ uint32_t Bs_h[16][SMS], Bs_l[16][SMS];

    const int tid  = threadIdx.x;
    const int lane = tid & 31;
    const int wid  = tid >> 5;
    const int warp_m = wid & 1;
    const int warp_n = wid >> 1;

    const int lr  = tid >> 1;
    const int lc0 = (tid & 1) * 8;

    float acc[4][4][4];
    #pragma unroll
    for (int f = 0; f < 4; f++)
        #pragma unroll
        for (int g = 0; g < 4; g++)
            #pragma unroll
            for (int e = 0; e < 4; e++) acc[f][g][e] = 0.f;

    for (int k0 = 0; k0 < 512; k0 += 16) {
        #pragma unroll
        for (int u = 0; u < 2; u++) {
            float4 va = *reinterpret_cast<const float4*>(&X[(size_t)(m0 + lr) * 512 + k0 + lc0 + u * 4]);
            float ea[4] = {va.x, va.y, va.z, va.w};
            float4 vb = *reinterpret_cast<const float4*>(&W[(size_t)(n0 + lr) * 512 + k0 + lc0 + u * 4]);
            float eb[4] = {vb.x, vb.y, vb.z, vb.w};
            #pragma unroll
            for (int j = 0; j < 4; j++) {
                int k = lc0 + u * 4 + j;
                uint32_t h, l;
                tf32_pair(ea[j], h, l);
                As_h[k][lr] = h; As_l[k][lr] = l;
                tf32_pair(eb[j], h, l);
                Bs_h[k][lr] = h; Bs_l[k][lr] = l;
            }
        }
        __syncthreads();

        #pragma unroll
        for (int ks = 0; ks < 2; ks++) {
            const int kb = ks * 8 + (lane & 3);
            uint32_t ah[4][4], al[4][4];
            #pragma unroll
            for (int f = 0; f < 4; f++) {
                int m = warp_m * 64 + f * 16 + (lane >> 2);
                ah[f][0] = As_h[kb][m];     ah[f][1] = As_h[kb][m + 8];
                ah[f][2] = As_h[kb + 4][m]; ah[f][3] = As_h[kb + 4][m + 8];
                al[f][0] = As_l[kb][m];     al[f][1] = As_l[kb][m + 8];
                al[f][2] = As_l[kb + 4][m]; al[f][3] = As_l[kb + 4][m + 8];
            }
            uint32_t bh[4][2], bl[4][2];
            #pragma unroll
            for (int g = 0; g < 4; g++) {
                int n = warp_n * 32 + g * 8 + (lane >> 2);
                bh[g][0] = Bs_h[kb][n]; bh[g][1] = Bs_h[kb + 4][n];
                bl[g][0] = Bs_l[kb][n]; bl[g][1] = Bs_l[kb + 4][n];
            }
            #pragma unroll
            for (int f = 0; f < 4; f++)
                #pragma unroll
                for (int g = 0; g < 4; g++) {
                    mma8(acc[f][g], ah[f], bh[g]);
                    mma8(acc[f][g], ah[f], bl[g]);
                    mma8(acc[f][g], al[f], bh[g]);
                }
        }
        __syncthreads();
    }

    #pragma unroll
    for (int f = 0; f < 4; f++) {
        const int m = m0 + warp_m * 64 + f * 16 + (lane >> 2);
        #pragma unroll
        for (int g = 0; g < 4; g++) {
            const int n = n0 + warp_n * 32 + g * 8 + (lane & 3) * 2;
            float b0 = 0.f, b1 = 0.f;
            if (has_bias) { b0 = bias[n]; b1 = bias[n + 1]; }
            float2 v0 = make_float2(acc[f][g][0] + b0, acc[f][g][1] + b1);
            float2 v1 = make_float2(acc[f][g][2] + b0, acc[f][g][3] + b1);
            *reinterpret_cast<float2*>(&out[(size_t)m * 512 + n]) = v0;
            *reinterpret_cast<float2*>(&out[(size_t)(m + 8) * 512 + n]) = v1;
        }
    }
}

__global__ void __launch_bounds__(256) gemm_qkv_tf32(
    const float* __restrict__ X,
    const float* __restrict__ Wq, const float* __restrict__ Wk, const float* __restrict__ Wv,
    float* __restrict__ Qo, float* __restrict__ Ko, float* __restrict__ Vo)
{
    const int bid = blockIdx.x;
    const int z = bid / 64, r = bid % 64;
    const float* W = (z == 0) ? Wq : (z == 1) ? Wk : Wv;
    float* out     = (z == 0) ? Qo : (z == 1) ? Ko : Vo;
    gemm_tf32_body(X, W, nullptr, out, (r >> 2) * 128, (r & 3) * 128, false);
}

__global__ void __launch_bounds__(256) gemm_proj_tf32(
    const float* __restrict__ X, const float* __restrict__ W,
    const float* __restrict__ bias, float* __restrict__ out)
{
    const int bid = blockIdx.x;
    gemm_tf32_body(X, W, bias, out, (bid >> 2) * 128, (bid & 3) * 128, true);
}

// ---------------------------------------------------------------------------
// Column sums of V, two-stage deterministic.
// ---------------------------------------------------------------------------
__global__ void __launch_bounds__(256) colsum_part(const float* __restrict__ V,
                                                   float (*__restrict__ csp)[BB*CC])
{
    const int b = blockIdx.y;
    const int z = blockIdx.z;
    const int c = blockIdx.x * 256 + threadIdx.x;
    const float* base = V + ((size_t)b * NN + z * 64) * CC + c;
    float s = 0.0f;
    #pragma unroll 8
    for (int n = 0; n < 64; n++)
        s += base[(size_t)n * CC];
    csp[z][b * CC + c] = s;
}

__global__ void __launch_bounds__(256) colsum_final(const float (*__restrict__ csp)[BB*CC],
                                                    float* __restrict__ cs)
{
    const int i = blockIdx.x * 256 + threadIdx.x;
    float s = 0.0f;
    #pragma unroll
    for (int z = 0; z < 16; z++) s += csp[z][i];
    cs[i] = s;
}

// ---------------------------------------------------------------------------
// Fused cluster-block attention on TENSOR CORES (3xTF32 mma for both gemms).
// Block = 256 threads = 8 warps as 4(m) x 2(n); tile 64(i) x 64(j), hd=64.
// smem tiles fp32: Q,K,E stride 68 (conflict-free m16n8k8 A/B frag loads),
// V stride 72 (conflict-free transposed B frag loads).
// ---------------------------------------------------------------------------
#define QS 68
#define VS 72
#define ATTN_SMEM ((3*64*QS + 64*VS + 2*64) * 4)   // 71,680 B

extern __shared__ float sm_dyn[];
__global__ void __launch_bounds__(256) cluster_attn(
    const float* __restrict__ Q, const float* __restrict__ K,
    const float* __restrict__ V,
    const int* __restrict__ mem, const int* __restrict__ cnt,
    const float* __restrict__ cs,
    float* __restrict__ Sc, float* __restrict__ O)
{
    const int bid = blockIdx.x;          // 512
    const int bch = bid >> 2;
    const int ti  = bid & 3;
    const int h  = bch & 7;
    const int bc = bch >> 3;
    const int b  = bc >> 3;
    const int Mc = cnt[bc];
    if (ti * 64 >= Mc) return;

    float* Qs = sm_dyn;                  // [64][QS]
    float* Ks = Qs + 64 * QS;
    float* Es = Ks + 64 * QS;
    float* Vs = Es + 64 * QS;            // [64][VS]
    float* RS = Vs + 64 * VS;            // [2][64] rowsum partials

    const int t    = threadIdx.x;
    const int lane = t & 31;
    const int w    = t >> 5;
    const int wm   = w & 3;              // m-slice (16 rows)
    const int wn   = w >> 2;             // n-slice (32 cols)
    const int m0   = wm * 16;
    const int n0   = wn * 32;
    const int lg   = lane >> 2;          // 0..7
    const int lt   = lane & 3;           // 0..3

    const int grow = t >> 2, quad = t & 3;   // tile-gather mapping
    const int* memb = mem + bc * NN;

    // ---- gather Q tile (once): Qs[i][k] ----
    {
        const int il = ti * 64 + grow;
        const int gi = (il < Mc) ? memb[il] : -1;
        const float* qb = (gi >= 0) ? Q + ((size_t)(b * NN + gi)) * CC + h * HD : nullptr;
        #pragma unroll
        for (int u = 0; u < 4; u++) {
            int k = quad * 16 + u * 4;
            float4 qv = qb ? *reinterpret_cast<const float4*>(qb + k)
                           : make_float4(0.f, 0.f, 0.f, 0.f);
            *reinterpret_cast<float4*>(&Qs[grow * QS + k]) = qv;
        }
    }

    float acc2[4][4];                    // [nb][reg] output accumulators
    #pragma unroll
    for (int nb = 0; nb < 4; nb++)
        #pragma unroll
        for (int e = 0; e < 4; e++) acc2[nb][e] = 0.f;
    float rs0 = 0.f, rs1 = 0.f;          // rowsum partials (rows m0+lg, +8)

    const int njt = (Mc + 63) >> 6;
    for (int jb = 0; jb < njt; jb++) {
        // ---- gather K, V tiles: Ks[j][k], Vs[j][d] ----
        {
            const int jl = jb * 64 + grow;
            const int gj = (jl < Mc) ? memb[jl] : -1;
            const float* kb = (gj >= 0) ? K + ((size_t)(b * NN + gj)) * CC + h * HD : nullptr;
            const float* vb = (gj >= 0) ? V + ((size_t)(b * NN + gj)) * CC + h * HD : nullptr;
            #pragma unroll
            for (int u = 0; u < 4; u++) {
                int k = quad * 16 + u * 4;
                float4 kv = kb ? *reinterpret_cast<const float4*>(kb + k)
                               : make_float4(0.f, 0.f, 0.f, 0.f);
                *reinterpret_cast<float4*>(&Ks[grow * QS + k]) = kv;
                float4 vv = vb ? *reinterpret_cast<const float4*>(vb + k)
                               : make_float4(0.f, 0.f, 0.f, 0.f);
                *reinterpret_cast<float4*>(&Vs[grow * VS + k]) = vv;
            }
        }
        __syncthreads();

        // ---- gemm1: S = Q K^T via 3xTF32 mma ----
        float c1[4][4];
        #pragma unroll
        for (int nb = 0; nb < 4; nb++)
            #pragma unroll
            for (int e = 0; e < 4; e++) c1[nb][e] = 0.f;

        #pragma unroll
        for (int kb = 0; kb < 8; kb++) {
            const int kk = kb * 8 + lt;
            float af[4] = { Qs[(m0 + lg) * QS + kk],     Qs[(m0 + lg + 8) * QS + kk],
                            Qs[(m0 + lg) * QS + kk + 4], Qs[(m0 + lg + 8) * QS + kk + 4] };
            uint32_t ah[4], al[4];
            #pragma unroll
            for (int e = 0; e < 4; e++) tf32_pair(af[e], ah[e], al[e]);
            #pragma unroll
            for (int nb = 0; nb < 4; nb++) {
                const int nj = n0 + nb * 8 + lg;
                float bf[2] = { Ks[nj * QS + kb * 8 + lt], Ks[nj * QS + kb * 8 + lt + 4] };
                uint32_t bh[2], bl[2];
                tf32_pair(bf[0], bh[0], bl[0]);
                tf32_pair(bf[1], bh[1], bl[1]);
                mma8(c1[nb], ah, bh);
                mma8(c1[nb], ah, bl);
                mma8(c1[nb], al, bh);
            }
        }

        // ---- epilogue: scale, mask, exp, Sc store, Es stage, rowsum ----
        {
            const int r0 = m0 + lg, r1 = m0 + lg + 8;
            const int pi0 = ti * 64 + r0, pi1 = ti * 64 + r1;
            #pragma unroll
            for (int nb = 0; nb < 4; nb++) {
                const int q0 = n0 + nb * 8 + 2 * lt;
                const int qj0 = jb * 64 + q0;
                float s00 = c1[nb][0] * SCALE, s01 = c1[nb][1] * SCALE;
                float s10 = c1[nb][2] * SCALE, s11 = c1[nb][3] * SCALE;
                bool v0c = (qj0 < Mc), v1c = (qj0 + 1 < Mc);
                float e00 = (pi0 < Mc && v0c && s00 != 0.f) ? __expf(s00) : 0.f;
                float e01 = (pi0 < Mc && v1c && s01 != 0.f) ? __expf(s01) : 0.f;
                float e10 = (pi1 < Mc && v0c && s10 != 0.f) ? __expf(s10) : 0.f;
                float e11 = (pi1 < Mc && v1c && s11 != 0.f) ? __expf(s11) : 0.f;
                // compact scores (only [0,Mc)^2 region ever read by compose)
                *reinterpret_cast<float2*>(&Sc[((size_t)bch * SC_CAP + pi0) * SC_CAP + qj0]) =
                    make_float2(s00, s01);
                *reinterpret_cast<float2*>(&Sc[((size_t)bch * SC_CAP + pi1) * SC_CAP + qj0]) =
                    make_float2(s10, s11);
                *reinterpret_cast<float2*>(&Es[r0 * QS + q0]) = make_float2(e00, e01);
                *reinterpret_cast<float2*>(&Es[r1 * QS + q0]) = make_float2(e10, e11);
                rs0 += e00 + e01;
                rs1 += e10 + e11;
            }
        }
        __syncthreads();

        // ---- gemm2: acc2 += E @ V via 3xTF32 mma (B = Vs transposed-index) ----
        #pragma unroll
        for (int kb = 0; kb < 8; kb++) {
            const int jj = kb * 8;
            float af[4] = { Es[(m0 + lg) * QS + jj + lt],     Es[(m0 + lg + 8) * QS + jj + lt],
                            Es[(m0 + lg) * QS + jj + lt + 4], Es[(m0 + lg + 8) * QS + jj + lt + 4] };
            uint32_t ah[4], al[4];
            #pragma unroll
            for (int e = 0; e < 4; e++) tf32_pair(af[e], ah[e], al[e]);
            #pragma unroll
            for (int nb = 0; nb < 4; nb++) {
                const int dd = n0 + nb * 8 + lg;
                float bf[2] = { Vs[(jj + lt) * VS + dd], Vs[(jj + lt + 4) * VS + dd] };
                uint32_t bh[2], bl[2];
                tf32_pair(bf[0], bh[0], bl[0]);
                tf32_pair(bf[1], bh[1], bl[1]);
                mma8(acc2[nb], ah, bh);
                mma8(acc2[nb], ah, bl);
                mma8(acc2[nb], al, bh);
            }
        }
        __syncthreads();
    }

    // ---- rowsum: reduce across the 4 lanes of each row group, then 2 wn warps
    rs0 += __shfl_xor_sync(0xffffffffu, rs0, 1);
    rs0 += __shfl_xor_sync(0xffffffffu, rs0, 2);
    rs1 += __shfl_xor_sync(0xffffffffu, rs1, 1);
    rs1 += __shfl_xor_sync(0xffffffffu, rs1, 2);
    if (lt == 0) {
        RS[wn * 64 + m0 + lg]     = rs0;
        RS[wn * 64 + m0 + lg + 8] = rs1;
    }
    __syncthreads();

    // ---- output: O = (acc2 + EPS_N * colsumV) / (rowsum + EPS) ----
    {
        const int r0 = m0 + lg, r1 = m0 + lg + 8;
        const int il0 = ti * 64 + r0, il1 = ti * 64 + r1;
        const int gi0 = (il0 < Mc) ? memb[il0] : -1;
        const int gi1 = (il1 < Mc) ? memb[il1] : -1;
        const float inv0 = 1.0f / (RS[r0] + RS[64 + r0] + EPS);
        const float inv1 = 1.0f / (RS[r1] + RS[64 + r1] + EPS);
        #pragma unroll
        for (int nb = 0; nb < 4; nb++) {
            const int d0 = n0 + nb * 8 + 2 * lt;
            const float cs0 = cs[b * CC + h * HD + d0];
            const float cs1 = cs[b * CC + h * HD + d0 + 1];
            if (gi0 >= 0) {
                float2 o = make_float2((acc2[nb][0] + EPS_N * cs0) * inv0,
                                       (acc2[nb][1] + EPS_N * cs1) * inv0);
                *reinterpret_cast<float2*>(&O[((size_t)(b * NN + gi0)) * CC + h * HD + d0]) = o;
            }
            if (gi1 >= 0) {
                float2 o = make_float2((acc2[nb][2] + EPS_N * cs0) * inv1,
                                       (acc2[nb][3] + EPS_N * cs1) * inv1);
                *reinterpret_cast<float2*>(&O[((size_t)(b * NN + gi1)) * CC + h * HD + d0]) = o;
            }
        }
    }
}

// ---------------------------------------------------------------------------
extern "C" void kernel_launch(void* const* d_in, const int* in_sizes, int n_in,
                              void* d_out, int out_size)
{
    const float* x_token = nullptr;
    const int*   idx     = nullptr;
    const float* Wmat[4] = {nullptr, nullptr, nullptr, nullptr};  // Wq,Wk,Wv,Wproj
    const float* bproj   = nullptr;
    int nW = 0;
    for (int i = 0; i < n_in; i++) {
        int s = in_sizes[i];
        if (s == OUT_ELEMS && !x_token)      x_token = (const float*)d_in[i];
        else if (s == 262144 && nW < 4)      Wmat[nW++] = (const float*)d_in[i];
        else if (s == 2048 && !idx)          idx = (const int*)d_in[i];
        else if (s == 512 && !bproj)         bproj = (const float*)d_in[i];
    }

    float *pQ, *pK, *pV, *pO, *pCS, *pSc;
    float (*pCSP)[BB*CC];
    int *pMem, *pCnt;
    cudaGetSymbolAddress((void**)&pQ,   g_Q);
    cudaGetSymbolAddress((void**)&pK,   g_Kb);
    cudaGetSymbolAddress((void**)&pV,   g_V);
    cudaGetSymbolAddress((void**)&pO,   g_O);
    cudaGetSymbolAddress((void**)&pCS,  g_colsum);
    cudaGetSymbolAddress((void**)&pCSP, g_csp);
    cudaGetSymbolAddress((void**)&pMem, g_mem);
    cudaGetSymbolAddress((void**)&pCnt, g_cnt);
    cudaGetSymbolAddress((void**)&pSc,  g_Sc);

    float* out = (float*)d_out;
    const bool has_map = ((size_t)out_size >= OUT_ELEMS + MAP_ELEMS);
    float* map = has_map ? out + OUT_ELEMS : nullptr;
    float4* map4 = reinterpret_cast<float4*>(map);

    static cudaStream_t s2 = nullptr;
    static cudaEvent_t evStart = nullptr, evFill = nullptr;
    if (!s2) {
        cudaStreamCreateWithFlags(&s2, cudaStreamNonBlocking);
        cudaEventCreateWithFlags(&evStart, cudaEventDisableTiming);
        cudaEventCreateWithFlags(&evFill,  cudaEventDisableTiming);
        cudaFuncSetAttribute(cluster_attn,
                             cudaFuncAttributeMaxDynamicSharedMemorySize, ATTN_SMEM);
    }

    // Fork at root: row-gated zero fill of non-member rows (idx-only dep).
    if (has_map) {
        cudaEventRecord(evStart, 0);
        cudaStreamWaitEvent(s2, evStart, 0);
        fill_rows<<<8192, 256, 0, s2>>>(idx, map4);
        cudaEventRecord(evFill, s2);
    }

    // Main chain: compaction -> QKV -> colsum -> attention -> proj -> compose.
    compact_kernel<<<BB * NCLUS, 32>>>(idx, pMem, pCnt);
    gemm_qkv_tf32<<<192, 256>>>(x_token, Wmat[0], Wmat[1], Wmat[2], pQ, pK, pV);
    colsum_part<<<dim3(CC / 256, BB, 16), 256>>>(pV, pCSP);
    colsum_final<<<(BB * CC) / 256, 256>>>(pCSP, pCS);
    cluster_attn<<<512, 256, ATTN_SMEM>>>(
        pQ, pK, pV, pMem, pCnt, pCS, has_map ? pSc : (float*)pSc, pO);
    gemm_proj_tf32<<<64, 256>>>(pO, Wmat[3], bproj, out);

    if (has_map) {
        // Member rows: disjoint from fill_rows, depends only on attn (main).
        compose_rows<<<dim3(SC_CAP, BB * NCLUS * HH), 128>>>(pSc, pMem, pCnt, map);
        cudaStreamWaitEvent(0, evFill, 0);   // join before capture ends
    }
}